// round 12
// baseline (speedup 1.0000x reference)
#include <cuda_runtime.h>
#include <cuda_bf16.h>
#include <math.h>
#include <stdint.h>

// ----- problem constants (B=16, T=512, D=512) -----
constexpr int Bn = 16;
constexpr int Tn = 512;
constexpr int Dn = 512;
constexpr int BT = Bn * Tn;            // 8192
constexpr int TOTPAD = 8320;           // 65*128 max bank rows (padded)
constexpr int NTP = 68;                // padded per-row tile stride (16B aligned)
constexpr int KC = 32;                 // K per chunk
constexpr int NKCH = Dn / KC;          // 16
constexpr int STRIDE_B = 80;           // bytes per smem row (32 bf16 + pad) - conflict-free
constexpr int OP_BYTES = 128 * STRIDE_B;        // 10240 per operand per stage
constexpr int STG_BYTES = 2 * OP_BYTES;         // 20480 (A then B)
constexpr int STAGES = 5;
constexpr int DYN_BYTES = STAGES * STG_BYTES;   // 102400
constexpr int NWORKERS = 296;
constexpr int DROWS = 64;              // rows per diag work item

// ----- device scratch (no allocations allowed) -----
__device__ __nv_bfloat16 g_hidb[2 * BT * Dn];    // [dir][row][512]
__device__ __nv_bfloat16 g_bankb[TOTPAD * Dn];   // zero-padded bank, bf16
__device__ int   g_src[TOTPAD];
__device__ int   g_rowhid[BT];
__device__ int   g_rowbatch[BT];
__device__ int   g_L[Bn];
__device__ float g_invL[Bn];
__device__ int   g_S, g_total, g_mt, g_ntl, g_nitems, g_ndiag, g_work;
__device__ __align__(16) float g_pm[2 * BT * NTP];   // [dir*BT + row][tile]
__device__ __align__(16) float g_ps[2 * BT * NTP];
__device__ float g_diag[2 * BT];
__device__ double g_acc[2];

// ----- helpers -----
__device__ __forceinline__ uint32_t smem_u32(const void* p) {
    uint32_t a;
    asm("{ .reg .u64 t; cvta.to.shared.u64 t, %1; cvt.u32.u64 %0, t; }" : "=r"(a) : "l"(p));
    return a;
}
__device__ __forceinline__ void cp16(uint32_t dst, const void* src) {
    asm volatile("cp.async.cg.shared.global [%0], [%1], 16;" :: "r"(dst), "l"(src) : "memory");
}
__device__ __forceinline__ void cp_commit() {
    asm volatile("cp.async.commit_group;" ::: "memory");
}
__device__ __forceinline__ void cp_wait3() {
    asm volatile("cp.async.wait_group 3;" ::: "memory");
}
__device__ __forceinline__ void ldsm_x4(uint32_t& r0, uint32_t& r1, uint32_t& r2, uint32_t& r3, uint32_t a) {
    asm volatile("ldmatrix.sync.aligned.m8n8.x4.shared.b16 {%0,%1,%2,%3}, [%4];"
                 : "=r"(r0), "=r"(r1), "=r"(r2), "=r"(r3) : "r"(a));
}
__device__ __forceinline__ void ldsm_x4t(uint32_t& r0, uint32_t& r1, uint32_t& r2, uint32_t& r3, uint32_t a) {
    asm volatile("ldmatrix.sync.aligned.m8n8.x4.trans.shared.b16 {%0,%1,%2,%3}, [%4];"
                 : "=r"(r0), "=r"(r1), "=r"(r2), "=r"(r3) : "r"(a));
}
__device__ __forceinline__ void mma16816(float* c, const uint32_t* a, uint32_t b0, uint32_t b1) {
    asm volatile("mma.sync.aligned.m16n8k16.row.col.f32.bf16.bf16.f32 "
                 "{%0,%1,%2,%3}, {%4,%5,%6,%7}, {%8,%9}, {%0,%1,%2,%3};"
                 : "+f"(c[0]), "+f"(c[1]), "+f"(c[2]), "+f"(c[3])
                 : "r"(a[0]), "r"(a[1]), "r"(a[2]), "r"(a[3]), "r"(b0), "r"(b1));
}
__device__ __forceinline__ uint32_t f2bf2(float lo, float hi) {
    uint32_t r;
    asm("cvt.rn.bf16x2.f32 %0, %1, %2;" : "=r"(r) : "f"(hi), "f"(lo));
    return r;
}

// ------------------------------------------------------------------
// 1) layout setup (single block)
// ------------------------------------------------------------------
__global__ void setup_kernel(const int* __restrict__ seq_lens) {
    __shared__ int sL[Bn], sCum[Bn + 1], sStart[Bn];
    int tid = threadIdx.x;
    if (tid == 0) {
        int c = 0;
        for (int i = 0; i < Bn; i++) {
            sL[i] = seq_lens[i];
            sCum[i] = c;
            sStart[i] = 2 * i + c;
            c += sL[i];
        }
        sCum[Bn] = c;
        g_S = c;
        g_total = c + 2 * Bn;
        g_mt = (c + 127) / 128;
        g_ntl = (g_total + 127) / 128;
        g_ndiag = (c + DROWS - 1) / DROWS;
        g_nitems = g_ndiag + g_mt * g_ntl * 2;
        g_work = 0;
        g_acc[0] = 0.0; g_acc[1] = 0.0;
    }
    __syncthreads();
    int S = sCum[Bn];
    int total = S + 2 * Bn;
    if (tid < Bn) { g_invL[tid] = 1.0f / (float)sL[tid]; g_L[tid] = sL[tid]; }

    for (int r = tid; r < TOTPAD; r += blockDim.x) {
        int src = -1;
        if (r < total) {
            for (int i = 0; i < Bn; i++) {
                int s0 = sStart[i];
                if (r >= s0 && r < s0 + sL[i] + 2) {
                    if (r > s0 && r < s0 + sL[i] + 1) src = i * Tn + (r - s0 - 1);
                    break;
                }
            }
        }
        g_src[r] = src;
    }
    for (int r = tid; r < BT; r += blockDim.x) {
        if (r < S) {
            int b = 0;
            for (int i = 0; i < Bn; i++)
                if (r >= sCum[i] && r < sCum[i + 1]) { b = i; break; }
            int t = r - sCum[b];
            g_rowhid[r] = b * Tn + t;
            g_rowbatch[r] = b;
        } else {
            g_rowhid[r] = 0; g_rowbatch[r] = 0;
        }
    }
}

// ------------------------------------------------------------------
// 2) fused conversion: hidden -> per-dir bf16, feats -> bf16 bank
// ------------------------------------------------------------------
__global__ void cvt_kernel(const float* __restrict__ hidden,
                           const float* __restrict__ feats) {
    int blk = blockIdx.x;
    int tid = threadIdx.x;
    if (blk < BT) {
        float4 v = reinterpret_cast<const float4*>(hidden)[blk * 256 + tid];
        int dir = tid >= 128;
        int col = tid * 4 - dir * 512;
        uint2 o = make_uint2(f2bf2(v.x, v.y), f2bf2(v.z, v.w));
        *reinterpret_cast<uint2*>(&g_hidb[((size_t)dir * BT + blk) * Dn + col]) = o;
    } else if (tid < 128) {
        int row = blk - BT;
        int src = g_src[row];
        float4 v = make_float4(0.f, 0.f, 0.f, 0.f);
        if (src >= 0) v = reinterpret_cast<const float4*>(feats)[src * 128 + tid];
        uint2 o = make_uint2(f2bf2(v.x, v.y), f2bf2(v.z, v.w));
        *reinterpret_cast<uint2*>(&g_bankb[(size_t)row * Dn + tid * 4]) = o;
    }
}

// ------------------------------------------------------------------
// 3) persistent worker: diag items first, then GEMM+LSE tiles
//    grid 296 x 256 threads
// ------------------------------------------------------------------
__global__ void __launch_bounds__(256, 2) lse_kernel(const float* __restrict__ hidden,
                                                     const float* __restrict__ feats) {
    extern __shared__ char dyn[];
    __shared__ int s_item;

    const int tid = threadIdx.x;
    const int warp = tid >> 5;
    const int lane = tid & 31;
    const uint32_t ring = smem_u32(dyn);

    const int S = g_S;
    const int total = g_total;
    const int mt = g_mt;
    const int ntl = g_ntl;
    const int ndiag = g_ndiag;
    const int nitems = g_nitems;

    // cp.async geometry: rows ra=tid>>2 and ra+64, seg tid&3
    const int ra = tid >> 2;
    const int seg = tid & 3;
    const uint32_t dA0 = ra * STRIDE_B + seg * 16;
    const uint32_t dA1 = dA0 + 64 * STRIDE_B;
    const uint32_t dB0 = OP_BYTES + dA0;
    const uint32_t dB1 = OP_BYTES + dA1;

    while (true) {
        if (tid == 0) s_item = atomicAdd(&g_work, 1);
        __syncthreads();                 // also guards smem ring reuse
        const int item = s_item;
        if (item >= nitems) break;

        if (item < ndiag) {
            // ---------------- diag item: exact fp32 dot products, 64 rows, both dirs ----------------
            const int r0 = item * DROWS;
#pragma unroll
            for (int g = 0; g < 8; g++) {
                int r = r0 + warp * 8 + g;
                if (r >= S) break;
                int hrow = g_rowhid[r];
                int b = hrow >> 9, t = hrow & 511;
#pragma unroll
                for (int dir = 0; dir < 2; dir++) {
                    bool ok = dir == 0 ? (t + 1 < g_L[b]) : (t > 0);
                    float sum = 0.f;
                    if (ok) {
                        int frow = hrow + (dir == 0 ? 1 : -1);
                        const float4* h = reinterpret_cast<const float4*>(hidden + (size_t)hrow * 1024 + dir * Dn);
                        const float4* x = reinterpret_cast<const float4*>(feats + (size_t)frow * Dn);
#pragma unroll
                        for (int j = 0; j < 4; j++) {
                            float4 a = h[lane + j * 32];
                            float4 c = x[lane + j * 32];
                            sum += a.x * c.x + a.y * c.y + a.z * c.z + a.w * c.w;
                        }
#pragma unroll
                        for (int o = 16; o >= 1; o >>= 1) sum += __shfl_xor_sync(0xffffffffu, sum, o);
                    }
                    if (lane == 0) g_diag[dir * BT + r] = sum;
                }
            }
            continue;
        }

        const int gi = item - ndiag;
        const int dir = gi / (mt * ntl);
        const int rem = gi % (mt * ntl);
        const int m = rem / ntl;
        const int n = rem % ntl;
        const int m0 = m * 128;
        const int n0 = n * 128;

        // source row pointers for this thread's cp.async rows
        const __nv_bfloat16* hb = g_hidb + (size_t)dir * BT * Dn;
        const __nv_bfloat16* a_src0 = hb + (size_t)g_rowhid[min(m0 + ra, S - 1)] * Dn + seg * 8;
        const __nv_bfloat16* a_src1 = hb + (size_t)g_rowhid[min(m0 + ra + 64, S - 1)] * Dn + seg * 8;
        const __nv_bfloat16* b_src0 = g_bankb + (size_t)(n0 + ra) * Dn + seg * 8;
        const __nv_bfloat16* b_src1 = b_src0 + (size_t)64 * Dn;

        auto issue = [&](int kc, int stg) {
            const uint32_t st = ring + stg * STG_BYTES;
            const int ko = kc * KC;
            cp16(st + dA0, a_src0 + ko);
            cp16(st + dA1, a_src1 + ko);
            cp16(st + dB0, b_src0 + ko);
            cp16(st + dB1, b_src1 + ko);
        };
#pragma unroll
        for (int p = 0; p < 4; p++) { issue(p, p); cp_commit(); }

        float acc[16][4];
#pragma unroll
        for (int q = 0; q < 16; q++)
#pragma unroll
            for (int j = 0; j < 4; j++) acc[q][j] = 0.f;

        for (int kc = 0; kc < NKCH; kc++) {
            cp_wait3();
            __syncthreads();
            int nx = kc + 4;
            if (nx < NKCH) issue(nx, nx % STAGES);
            cp_commit();   // real or empty group keeps wait_group 3 invariant

            const uint32_t stA = ring + (kc % STAGES) * STG_BYTES;
            const uint32_t stB = stA + OP_BYTES;
            uint32_t a[2][4];
            {
                uint32_t aaddr = stA + (warp * 16 + (lane & 15)) * STRIDE_B + ((lane >> 4) << 4);
                ldsm_x4(a[0][0], a[0][1], a[0][2], a[0][3], aaddr);
                ldsm_x4(a[1][0], a[1][1], a[1][2], a[1][3], aaddr + 32);
            }
#pragma unroll
            for (int q = 0; q < 16; q++) {
                uint32_t baddr = stB + (q * 8 + (lane & 7)) * STRIDE_B + (((lane >> 3) & 3) << 4);
                uint32_t b0, b1, b2, b3;
                ldsm_x4t(b0, b1, b2, b3, baddr);
                mma16816(acc[q], a[0], b0, b1);
                mma16816(acc[q], a[1], b2, b3);
            }
        }

        // ---- per-tile LSE fold (rows lane>>2 and +8 of this warp's 16) ----
        if (n0 + 128 > total) {
            int cb = n0 + (lane & 3) * 2;
#pragma unroll
            for (int q = 0; q < 16; q++) {
                int c = cb + q * 8;
                if (c >= total)     { acc[q][0] = -INFINITY; acc[q][2] = -INFINITY; }
                if (c + 1 >= total) { acc[q][1] = -INFINITY; acc[q][3] = -INFINITY; }
            }
        }
        float m0l = -INFINITY, m1l = -INFINITY;
#pragma unroll
        for (int q = 0; q < 16; q++) {
            m0l = fmaxf(m0l, fmaxf(acc[q][0], acc[q][1]));
            m1l = fmaxf(m1l, fmaxf(acc[q][2], acc[q][3]));
        }
        m0l = fmaxf(m0l, __shfl_xor_sync(0xffffffffu, m0l, 1));
        m0l = fmaxf(m0l, __shfl_xor_sync(0xffffffffu, m0l, 2));
        m1l = fmaxf(m1l, __shfl_xor_sync(0xffffffffu, m1l, 1));
        m1l = fmaxf(m1l, __shfl_xor_sync(0xffffffffu, m1l, 2));
        m0l = fmaxf(m0l, -1e30f);
        m1l = fmaxf(m1l, -1e30f);
        float s0 = 0.f, s1 = 0.f;
#pragma unroll
        for (int q = 0; q < 16; q++) {
            s0 += __expf(acc[q][0] - m0l) + __expf(acc[q][1] - m0l);
            s1 += __expf(acc[q][2] - m1l) + __expf(acc[q][3] - m1l);
        }
        s0 += __shfl_xor_sync(0xffffffffu, s0, 1);
        s0 += __shfl_xor_sync(0xffffffffu, s0, 2);
        s1 += __shfl_xor_sync(0xffffffffu, s1, 1);
        s1 += __shfl_xor_sync(0xffffffffu, s1, 2);

        if ((lane & 3) == 0) {
            int r0 = m0 + warp * 16 + (lane >> 2);
            size_t base = (size_t)(dir * BT) * NTP + n;
            g_pm[base + (size_t)r0 * NTP] = m0l;       g_ps[base + (size_t)r0 * NTP] = s0;
            g_pm[base + (size_t)(r0 + 8) * NTP] = m1l; g_ps[base + (size_t)(r0 + 8) * NTP] = s1;
        }
    }
}

// ------------------------------------------------------------------
// 4) combine: one warp per (row, dir); lanes cover tiles in parallel,
//    coalesced partial reads, shuffle reduce, REDG into g_acc
// ------------------------------------------------------------------
__global__ void combine_kernel() {
    int tid = threadIdx.x;
    int warp = tid >> 5;
    int lane = tid & 31;
    int idx = blockIdx.x * 8 + warp;      // (row, dir) pair over 2*BT
    int S = g_S, ntl = g_ntl;
    int dir = idx >= BT;
    int r = idx - dir * BT;
    if (r >= S) return;

    const float* pm = g_pm + (size_t)(dir * BT + r) * NTP;
    const float* ps = g_ps + (size_t)(dir * BT + r) * NTP;

    // lanes cover tiles: c = lane, lane+32, lane+64 (ntl <= 65)
    float m0 = (lane < ntl)      ? pm[lane]      : -INFINITY;
    float m1 = (lane + 32 < ntl) ? pm[lane + 32] : -INFINITY;
    float m2 = (lane + 64 < ntl) ? pm[lane + 64] : -INFINITY;
    float s0 = (lane < ntl)      ? ps[lane]      : 0.f;
    float s1 = (lane + 32 < ntl) ? ps[lane + 32] : 0.f;
    float s2 = (lane + 64 < ntl) ? ps[lane + 64] : 0.f;

    float M = fmaxf(fmaxf(m0, m1), m2);
#pragma unroll
    for (int o = 16; o >= 1; o >>= 1) M = fmaxf(M, __shfl_xor_sync(0xffffffffu, M, o));

    float s = 0.f;
    if (s0 > 0.f) s += s0 * __expf(m0 - M);
    if (s1 > 0.f) s += s1 * __expf(m1 - M);
    if (s2 > 0.f) s += s2 * __expf(m2 - M);
#pragma unroll
    for (int o = 16; o >= 1; o >>= 1) s += __shfl_xor_sync(0xffffffffu, s, o);

    if (lane == 0) {
        float lse = M + logf(s);
        double a = (double)(lse - g_diag[dir * BT + r]) * (double)g_invL[g_rowbatch[r]];
        atomicAdd(&g_acc[dir], a);
    }
}

// ------------------------------------------------------------------
// 5) finalize -> out[0]=fw_loss, out[1]=bw_loss
// ------------------------------------------------------------------
__global__ void final_kernel(float* __restrict__ out) {
    if (threadIdx.x == 0) {
        out[0] = (float)(g_acc[0] / (double)Bn);
        out[1] = (float)(g_acc[1] / (double)Bn);
    }
}

// ------------------------------------------------------------------
extern "C" void kernel_launch(void* const* d_in, const int* in_sizes, int n_in,
                              void* d_out, int out_size) {
    const float* feats    = (const float*)d_in[0];
    const float* hidden   = (const float*)d_in[1];
    const int*   seq_lens = (const int*)d_in[2];
    float* out = (float*)d_out;

    cudaFuncSetAttribute(lse_kernel, cudaFuncAttributeMaxDynamicSharedMemorySize, DYN_BYTES);

    setup_kernel<<<1, 256>>>(seq_lens);
    cvt_kernel<<<BT + TOTPAD, 256>>>(hidden, feats);
    lse_kernel<<<NWORKERS, 256, DYN_BYTES>>>(hidden, feats);
    combine_kernel<<<2 * BT / 8, 256>>>();
    final_kernel<<<1, 32>>>(out);
    (void)in_sizes; (void)n_in; (void)out_size;
}

// round 13
// speedup vs baseline: 1.0358x; 1.0358x over previous
#include <cuda_runtime.h>
#include <cuda_bf16.h>
#include <math.h>
#include <stdint.h>

// ----- problem constants (B=16, T=512, D=512) -----
constexpr int Bn = 16;
constexpr int Tn = 512;
constexpr int Dn = 512;
constexpr int BT = Bn * Tn;            // 8192
constexpr int TOTPAD = 8320;           // 65*128 max bank rows (padded)
constexpr int NTP = 68;                // padded per-row tile stride (16B aligned)
constexpr int KC = 32;                 // K per chunk
constexpr int NKCH = Dn / KC;          // 16
constexpr int STRIDE_B = 80;           // bytes per smem row (32 bf16 + pad) - conflict-free
constexpr int OP_BYTES = 128 * STRIDE_B;        // 10240 per operand per stage
constexpr int STG_BYTES = 2 * OP_BYTES;         // 20480 (A then B)
constexpr int STAGES = 5;
constexpr int DYN_BYTES = STAGES * STG_BYTES;   // 102400
constexpr int NWORKERS = 296;
constexpr int DROWS = 64;              // rows per diag work item
constexpr int CBLK = 2 * BT / 8;       // 2048 combine blocks (8 pairs each)

// ----- device scratch (no allocations allowed) -----
__device__ __nv_bfloat16 g_hidb[2 * BT * Dn];    // [dir][row][512]
__device__ __nv_bfloat16 g_bankb[TOTPAD * Dn];   // zero-padded bank, bf16
__device__ int   g_src[TOTPAD];
__device__ int   g_rowhid[BT];
__device__ int   g_rowbatch[BT];
__device__ int   g_L[Bn];
__device__ float g_invL[Bn];
__device__ int   g_S, g_total, g_mt, g_ntl, g_nitems, g_ndiag, g_work;
__device__ __align__(16) float g_pm[2 * BT * NTP];   // [dir*BT + row][tile]
__device__ __align__(16) float g_ps[2 * BT * NTP];
__device__ float g_diag[2 * BT];
__device__ double g_part[2][CBLK];               // per-block per-dir partials

// ----- helpers -----
__device__ __forceinline__ uint32_t smem_u32(const void* p) {
    uint32_t a;
    asm("{ .reg .u64 t; cvta.to.shared.u64 t, %1; cvt.u32.u64 %0, t; }" : "=r"(a) : "l"(p));
    return a;
}
__device__ __forceinline__ void cp16(uint32_t dst, const void* src) {
    asm volatile("cp.async.cg.shared.global [%0], [%1], 16;" :: "r"(dst), "l"(src) : "memory");
}
__device__ __forceinline__ void cp_commit() {
    asm volatile("cp.async.commit_group;" ::: "memory");
}
__device__ __forceinline__ void cp_wait3() {
    asm volatile("cp.async.wait_group 3;" ::: "memory");
}
__device__ __forceinline__ void ldsm_x4(uint32_t& r0, uint32_t& r1, uint32_t& r2, uint32_t& r3, uint32_t a) {
    asm volatile("ldmatrix.sync.aligned.m8n8.x4.shared.b16 {%0,%1,%2,%3}, [%4];"
                 : "=r"(r0), "=r"(r1), "=r"(r2), "=r"(r3) : "r"(a));
}
__device__ __forceinline__ void ldsm_x4t(uint32_t& r0, uint32_t& r1, uint32_t& r2, uint32_t& r3, uint32_t a) {
    asm volatile("ldmatrix.sync.aligned.m8n8.x4.trans.shared.b16 {%0,%1,%2,%3}, [%4];"
                 : "=r"(r0), "=r"(r1), "=r"(r2), "=r"(r3) : "r"(a));
}
__device__ __forceinline__ void mma16816(float* c, const uint32_t* a, uint32_t b0, uint32_t b1) {
    asm volatile("mma.sync.aligned.m16n8k16.row.col.f32.bf16.bf16.f32 "
                 "{%0,%1,%2,%3}, {%4,%5,%6,%7}, {%8,%9}, {%0,%1,%2,%3};"
                 : "+f"(c[0]), "+f"(c[1]), "+f"(c[2]), "+f"(c[3])
                 : "r"(a[0]), "r"(a[1]), "r"(a[2]), "r"(a[3]), "r"(b0), "r"(b1));
}
__device__ __forceinline__ uint32_t f2bf2(float lo, float hi) {
    uint32_t r;
    asm("cvt.rn.bf16x2.f32 %0, %1, %2;" : "=r"(r) : "f"(hi), "f"(lo));
    return r;
}

// ------------------------------------------------------------------
// 1) layout setup (single block)
// ------------------------------------------------------------------
__global__ void setup_kernel(const int* __restrict__ seq_lens) {
    __shared__ int sL[Bn], sCum[Bn + 1], sStart[Bn];
    int tid = threadIdx.x;
    if (tid == 0) {
        int c = 0;
        for (int i = 0; i < Bn; i++) {
            sL[i] = seq_lens[i];
            sCum[i] = c;
            sStart[i] = 2 * i + c;
            c += sL[i];
        }
        sCum[Bn] = c;
        g_S = c;
        g_total = c + 2 * Bn;
        g_mt = (c + 127) / 128;
        g_ntl = (g_total + 127) / 128;
        g_ndiag = (c + DROWS - 1) / DROWS;
        g_nitems = g_ndiag + g_mt * g_ntl * 2;
        g_work = 0;
    }
    __syncthreads();
    int S = sCum[Bn];
    int total = S + 2 * Bn;
    if (tid < Bn) { g_invL[tid] = 1.0f / (float)sL[tid]; g_L[tid] = sL[tid]; }

    for (int r = tid; r < TOTPAD; r += blockDim.x) {
        int src = -1;
        if (r < total) {
            for (int i = 0; i < Bn; i++) {
                int s0 = sStart[i];
                if (r >= s0 && r < s0 + sL[i] + 2) {
                    if (r > s0 && r < s0 + sL[i] + 1) src = i * Tn + (r - s0 - 1);
                    break;
                }
            }
        }
        g_src[r] = src;
    }
    for (int r = tid; r < BT; r += blockDim.x) {
        if (r < S) {
            int b = 0;
            for (int i = 0; i < Bn; i++)
                if (r >= sCum[i] && r < sCum[i + 1]) { b = i; break; }
            int t = r - sCum[b];
            g_rowhid[r] = b * Tn + t;
            g_rowbatch[r] = b;
        } else {
            g_rowhid[r] = 0; g_rowbatch[r] = 0;
        }
    }
}

// ------------------------------------------------------------------
// 2) fused conversion: hidden -> per-dir bf16, feats -> bf16 bank
// ------------------------------------------------------------------
__global__ void cvt_kernel(const float* __restrict__ hidden,
                           const float* __restrict__ feats) {
    int blk = blockIdx.x;
    int tid = threadIdx.x;
    if (blk < BT) {
        float4 v = reinterpret_cast<const float4*>(hidden)[blk * 256 + tid];
        int dir = tid >= 128;
        int col = tid * 4 - dir * 512;
        uint2 o = make_uint2(f2bf2(v.x, v.y), f2bf2(v.z, v.w));
        *reinterpret_cast<uint2*>(&g_hidb[((size_t)dir * BT + blk) * Dn + col]) = o;
    } else if (tid < 128) {
        int row = blk - BT;
        int src = g_src[row];
        float4 v = make_float4(0.f, 0.f, 0.f, 0.f);
        if (src >= 0) v = reinterpret_cast<const float4*>(feats)[src * 128 + tid];
        uint2 o = make_uint2(f2bf2(v.x, v.y), f2bf2(v.z, v.w));
        *reinterpret_cast<uint2*>(&g_bankb[(size_t)row * Dn + tid * 4]) = o;
    }
}

// ------------------------------------------------------------------
// 3) persistent worker: diag items first, then GEMM+LSE tiles
//    grid 296 x 256 threads
// ------------------------------------------------------------------
__global__ void __launch_bounds__(256, 2) lse_kernel(const float* __restrict__ hidden,
                                                     const float* __restrict__ feats) {
    extern __shared__ char dyn[];
    __shared__ int s_item;

    const int tid = threadIdx.x;
    const int warp = tid >> 5;
    const int lane = tid & 31;
    const uint32_t ring = smem_u32(dyn);

    const int S = g_S;
    const int total = g_total;
    const int mt = g_mt;
    const int ntl = g_ntl;
    const int ndiag = g_ndiag;
    const int nitems = g_nitems;

    // cp.async geometry: rows ra=tid>>2 and ra+64, seg tid&3
    const int ra = tid >> 2;
    const int seg = tid & 3;
    const uint32_t dA0 = ra * STRIDE_B + seg * 16;
    const uint32_t dA1 = dA0 + 64 * STRIDE_B;
    const uint32_t dB0 = OP_BYTES + dA0;
    const uint32_t dB1 = OP_BYTES + dA1;

    while (true) {
        if (tid == 0) s_item = atomicAdd(&g_work, 1);
        __syncthreads();                 // also guards smem ring reuse
        const int item = s_item;
        if (item >= nitems) break;

        if (item < ndiag) {
            // ---------------- diag item: exact fp32 dot products, 64 rows, both dirs ----------------
            const int r0 = item * DROWS;
#pragma unroll
            for (int g = 0; g < 8; g++) {
                int r = r0 + warp * 8 + g;
                if (r >= S) break;
                int hrow = g_rowhid[r];
                int b = hrow >> 9, t = hrow & 511;
#pragma unroll
                for (int dir = 0; dir < 2; dir++) {
                    bool ok = dir == 0 ? (t + 1 < g_L[b]) : (t > 0);
                    float sum = 0.f;
                    if (ok) {
                        int frow = hrow + (dir == 0 ? 1 : -1);
                        const float4* h = reinterpret_cast<const float4*>(hidden + (size_t)hrow * 1024 + dir * Dn);
                        const float4* x = reinterpret_cast<const float4*>(feats + (size_t)frow * Dn);
#pragma unroll
                        for (int j = 0; j < 4; j++) {
                            float4 a = h[lane + j * 32];
                            float4 c = x[lane + j * 32];
                            sum += a.x * c.x + a.y * c.y + a.z * c.z + a.w * c.w;
                        }
#pragma unroll
                        for (int o = 16; o >= 1; o >>= 1) sum += __shfl_xor_sync(0xffffffffu, sum, o);
                    }
                    if (lane == 0) g_diag[dir * BT + r] = sum;
                }
            }
            continue;
        }

        const int gi = item - ndiag;
        const int dir = gi / (mt * ntl);
        const int rem = gi % (mt * ntl);
        const int m = rem / ntl;
        const int n = rem % ntl;
        const int m0 = m * 128;
        const int n0 = n * 128;

        // source row pointers for this thread's cp.async rows
        const __nv_bfloat16* hb = g_hidb + (size_t)dir * BT * Dn;
        const __nv_bfloat16* a_src0 = hb + (size_t)g_rowhid[min(m0 + ra, S - 1)] * Dn + seg * 8;
        const __nv_bfloat16* a_src1 = hb + (size_t)g_rowhid[min(m0 + ra + 64, S - 1)] * Dn + seg * 8;
        const __nv_bfloat16* b_src0 = g_bankb + (size_t)(n0 + ra) * Dn + seg * 8;
        const __nv_bfloat16* b_src1 = b_src0 + (size_t)64 * Dn;

        auto issue = [&](int kc, int stg) {
            const uint32_t st = ring + stg * STG_BYTES;
            const int ko = kc * KC;
            cp16(st + dA0, a_src0 + ko);
            cp16(st + dA1, a_src1 + ko);
            cp16(st + dB0, b_src0 + ko);
            cp16(st + dB1, b_src1 + ko);
        };
#pragma unroll
        for (int p = 0; p < 4; p++) { issue(p, p); cp_commit(); }

        float acc[16][4];
#pragma unroll
        for (int q = 0; q < 16; q++)
#pragma unroll
            for (int j = 0; j < 4; j++) acc[q][j] = 0.f;

        for (int kc = 0; kc < NKCH; kc++) {
            cp_wait3();
            __syncthreads();
            int nx = kc + 4;
            if (nx < NKCH) issue(nx, nx % STAGES);
            cp_commit();   // real or empty group keeps wait_group 3 invariant

            const uint32_t stA = ring + (kc % STAGES) * STG_BYTES;
            const uint32_t stB = stA + OP_BYTES;
            uint32_t a[2][4];
            {
                uint32_t aaddr = stA + (warp * 16 + (lane & 15)) * STRIDE_B + ((lane >> 4) << 4);
                ldsm_x4(a[0][0], a[0][1], a[0][2], a[0][3], aaddr);
                ldsm_x4(a[1][0], a[1][1], a[1][2], a[1][3], aaddr + 32);
            }
#pragma unroll
            for (int q = 0; q < 16; q++) {
                uint32_t baddr = stB + (q * 8 + (lane & 7)) * STRIDE_B + (((lane >> 3) & 3) << 4);
                uint32_t b0, b1, b2, b3;
                ldsm_x4t(b0, b1, b2, b3, baddr);
                mma16816(acc[q], a[0], b0, b1);
                mma16816(acc[q], a[1], b2, b3);
            }
        }

        // ---- per-tile LSE fold (rows lane>>2 and +8 of this warp's 16) ----
        if (n0 + 128 > total) {
            int cb = n0 + (lane & 3) * 2;
#pragma unroll
            for (int q = 0; q < 16; q++) {
                int c = cb + q * 8;
                if (c >= total)     { acc[q][0] = -INFINITY; acc[q][2] = -INFINITY; }
                if (c + 1 >= total) { acc[q][1] = -INFINITY; acc[q][3] = -INFINITY; }
            }
        }
        float m0l = -INFINITY, m1l = -INFINITY;
#pragma unroll
        for (int q = 0; q < 16; q++) {
            m0l = fmaxf(m0l, fmaxf(acc[q][0], acc[q][1]));
            m1l = fmaxf(m1l, fmaxf(acc[q][2], acc[q][3]));
        }
        m0l = fmaxf(m0l, __shfl_xor_sync(0xffffffffu, m0l, 1));
        m0l = fmaxf(m0l, __shfl_xor_sync(0xffffffffu, m0l, 2));
        m1l = fmaxf(m1l, __shfl_xor_sync(0xffffffffu, m1l, 1));
        m1l = fmaxf(m1l, __shfl_xor_sync(0xffffffffu, m1l, 2));
        m0l = fmaxf(m0l, -1e30f);
        m1l = fmaxf(m1l, -1e30f);
        float s0 = 0.f, s1 = 0.f;
#pragma unroll
        for (int q = 0; q < 16; q++) {
            s0 += __expf(acc[q][0] - m0l) + __expf(acc[q][1] - m0l);
            s1 += __expf(acc[q][2] - m1l) + __expf(acc[q][3] - m1l);
        }
        s0 += __shfl_xor_sync(0xffffffffu, s0, 1);
        s0 += __shfl_xor_sync(0xffffffffu, s0, 2);
        s1 += __shfl_xor_sync(0xffffffffu, s1, 1);
        s1 += __shfl_xor_sync(0xffffffffu, s1, 2);

        if ((lane & 3) == 0) {
            int r0 = m0 + warp * 16 + (lane >> 2);
            size_t base = (size_t)(dir * BT) * NTP + n;
            g_pm[base + (size_t)r0 * NTP] = m0l;       g_ps[base + (size_t)r0 * NTP] = s0;
            g_pm[base + (size_t)(r0 + 8) * NTP] = m1l; g_ps[base + (size_t)(r0 + 8) * NTP] = s1;
        }
    }
}

// ------------------------------------------------------------------
// 4) combine: one warp per (row, dir); lanes cover tiles in parallel,
//    per-block per-dir partials stored contention-free (no atomics)
// ------------------------------------------------------------------
__global__ void combine_kernel() {
    __shared__ double shd[2][8];
    int tid = threadIdx.x;
    int warp = tid >> 5;
    int lane = tid & 31;
    int idx = blockIdx.x * 8 + warp;      // (row, dir) pair over 2*BT
    int S = g_S, ntl = g_ntl;
    int dir = idx >= BT;
    int r = idx - dir * BT;

    double a = 0.0;
    if (r < S) {
        const float* pm = g_pm + (size_t)(dir * BT + r) * NTP;
        const float* ps = g_ps + (size_t)(dir * BT + r) * NTP;

        // lanes cover tiles: c = lane, lane+32, lane+64 (ntl <= 65)
        float m0 = (lane < ntl)      ? pm[lane]      : -INFINITY;
        float m1 = (lane + 32 < ntl) ? pm[lane + 32] : -INFINITY;
        float m2 = (lane + 64 < ntl) ? pm[lane + 64] : -INFINITY;
        float s0 = (lane < ntl)      ? ps[lane]      : 0.f;
        float s1 = (lane + 32 < ntl) ? ps[lane + 32] : 0.f;
        float s2 = (lane + 64 < ntl) ? ps[lane + 64] : 0.f;

        float M = fmaxf(fmaxf(m0, m1), m2);
#pragma unroll
        for (int o = 16; o >= 1; o >>= 1) M = fmaxf(M, __shfl_xor_sync(0xffffffffu, M, o));

        float s = 0.f;
        if (s0 > 0.f) s += s0 * __expf(m0 - M);
        if (s1 > 0.f) s += s1 * __expf(m1 - M);
        if (s2 > 0.f) s += s2 * __expf(m2 - M);
#pragma unroll
        for (int o = 16; o >= 1; o >>= 1) s += __shfl_xor_sync(0xffffffffu, s, o);

        float lse = M + logf(s);
        a = (double)(lse - g_diag[dir * BT + r]) * (double)g_invL[g_rowbatch[r]];
    }
    if (lane == 0) { shd[0][warp] = dir ? 0.0 : a; shd[1][warp] = dir ? a : 0.0; }
    __syncthreads();
    if (tid < 2) {
        double v = 0.0;
#pragma unroll
        for (int w = 0; w < 8; w++) v += shd[tid][w];
        g_part[tid][blockIdx.x] = v;
    }
}

// ------------------------------------------------------------------
// 5) finalize: reduce per-block partials -> out[0], out[1]
// ------------------------------------------------------------------
__global__ void final_kernel(float* __restrict__ out) {
    __shared__ double sh[256][2];
    int tid = threadIdx.x;
    double a0 = 0.0, a1 = 0.0;
    for (int i = tid; i < CBLK; i += 256) {
        a0 += g_part[0][i];
        a1 += g_part[1][i];
    }
    sh[tid][0] = a0; sh[tid][1] = a1;
    __syncthreads();
    for (int o = 128; o >= 1; o >>= 1) {
        if (tid < o) { sh[tid][0] += sh[tid + o][0]; sh[tid][1] += sh[tid + o][1]; }
        __syncthreads();
    }
    if (tid == 0) {
        out[0] = (float)(sh[0][0] / (double)Bn);
        out[1] = (float)(sh[0][1] / (double)Bn);
    }
}

// ------------------------------------------------------------------
extern "C" void kernel_launch(void* const* d_in, const int* in_sizes, int n_in,
                              void* d_out, int out_size) {
    const float* feats    = (const float*)d_in[0];
    const float* hidden   = (const float*)d_in[1];
    const int*   seq_lens = (const int*)d_in[2];
    float* out = (float*)d_out;

    cudaFuncSetAttribute(lse_kernel, cudaFuncAttributeMaxDynamicSharedMemorySize, DYN_BYTES);

    setup_kernel<<<1, 256>>>(seq_lens);
    cvt_kernel<<<BT + TOTPAD, 256>>>(hidden, feats);
    lse_kernel<<<NWORKERS, 256, DYN_BYTES>>>(hidden, feats);
    combine_kernel<<<CBLK, 256>>>();
    final_kernel<<<1, 256>>>(out);
    (void)in_sizes; (void)n_in; (void)out_size;
}